// round 4
// baseline (speedup 1.0000x reference)
#include <cuda_runtime.h>

// 24-qubit state-vector sim, 8 two-qubit gates, step s -> qubits (s, s+7).
// Two passes of 4 gates; gates fused in PAIRS in registers (16-amp supergroup
// per thread). R4: packed gate weights live in SHARED memory and are streamed
// row-wise (broadcast LDS), cutting per-thread live regs from ~128 to ~85 so
// 3 CTAs/SM fit (occ 23.7% -> ~36%). Swizzle SWZ is bank-conflict-free for
// every access pattern (stage/writeout + all 4 pair patterns).

#define NSTATE (1u << 24)
typedef unsigned long long u64;

__device__ __forceinline__ u64 pk2(float lo, float hi) {
    u64 r; asm("mov.b64 %0, {%1, %2};" : "=l"(r) : "f"(lo), "f"(hi)); return r;
}
__device__ __forceinline__ void upk2(u64 v, float& lo, float& hi) {
    asm("mov.b64 {%0, %1}, %2;" : "=f"(lo), "=f"(hi) : "l"(v));
}
__device__ __forceinline__ u64 ffma2(u64 a, u64 b, u64 c) {
    u64 d; asm("fma.rn.f32x2 %0, %1, %2, %3;" : "=l"(d) : "l"(a), "l"(b), "l"(c)); return d;
}
__device__ __forceinline__ u64 fmul2(u64 a, u64 b) {
    u64 d; asm("mul.rn.f32x2 %0, %1, %2;" : "=l"(d) : "l"(a), "l"(b)); return d;
}
__device__ __forceinline__ unsigned SWZ(unsigned x) {
    return x ^ (((x >> 5) & 1u) * 10u) ^ (((x >> 6) & 1u) * 21u);
}

// Gate A within a pair varies amp-index bits (0,2); gate B varies bits (1,3).
__device__ __constant__ unsigned char QA[4][4] =
    {{0,1,4,5},{2,3,6,7},{8,9,12,13},{10,11,14,15}};
__device__ __constant__ unsigned char QB[4][4] =
    {{0,2,8,10},{1,3,9,11},{4,6,12,14},{5,7,13,15}};

// dst[q[i][g]] = row g of gate applied to src amps of quad i.
// Weights streamed from smem: wa row = (wr,wr) x4, wb row = (wi,wi) x4.
__device__ __forceinline__ void apply_gate16(u64* dst, const u64* src,
                                             const unsigned char (&qx)[4][4],
                                             const u64* __restrict__ swa,
                                             const u64* __restrict__ swb)
{
    #pragma unroll
    for (int g = 0; g < 4; ++g) {
        u64 wa0 = swa[g*4+0], wa1 = swa[g*4+1], wa2 = swa[g*4+2], wa3 = swa[g*4+3];
        u64 wb0 = swb[g*4+0], wb1 = swb[g*4+1], wb2 = swb[g*4+2], wb3 = swb[g*4+3];
        #pragma unroll
        for (int q = 0; q < 4; ++q) {
            u64 s0 = src[qx[q][0]], s1 = src[qx[q][1]];
            u64 s2 = src[qx[q][2]], s3 = src[qx[q][3]];
            u64 a1 = fmul2(s0, wa0);
            a1 = ffma2(s1, wa1, a1);
            a1 = ffma2(s2, wa2, a1);
            a1 = ffma2(s3, wa3, a1);
            u64 a2 = fmul2(s0, wb0);
            a2 = ffma2(s1, wb1, a2);
            a2 = ffma2(s2, wb2, a2);
            a2 = ffma2(s3, wb3, a2);
            float r1, i1, r2, i2; upk2(a1, r1, i1); upk2(a2, r2, i2);
            dst[qx[q][g]] = pk2(r1 - i2, i1 + r2);
        }
    }
}

template <int P0, int P1, int P2, int P3>
__device__ __forceinline__ void apply_pair(float2* sm, unsigned tid,
                                           const u64* swa0, const u64* swb0,
                                           const u64* swa1, const u64* swb1)
{
    unsigned x = tid;
    x = ((x & ~((1u << P0) - 1u)) << 1) | (x & ((1u << P0) - 1u));
    x = ((x & ~((1u << P1) - 1u)) << 1) | (x & ((1u << P1) - 1u));
    x = ((x & ~((1u << P2) - 1u)) << 1) | (x & ((1u << P2) - 1u));
    x = ((x & ~((1u << P3) - 1u)) << 1) | (x & ((1u << P3) - 1u));

    u64 p[16], o[16];
    #pragma unroll
    for (int i = 0; i < 16; ++i) {
        unsigned off = ((i & 1)        ? (1u << P0) : 0u)
                     | (((i >> 1) & 1) ? (1u << P1) : 0u)
                     | (((i >> 2) & 1) ? (1u << P2) : 0u)
                     | (((i >> 3) & 1) ? (1u << P3) : 0u);
        float2 v = sm[SWZ(x | off)];
        p[i] = pk2(v.x, v.y);
    }

    apply_gate16(o, p, QA, swa0, swb0);   // first gate of pair (bits P0,P2)
    apply_gate16(p, o, QB, swa1, swb1);   // second gate (bits P1,P3)

    #pragma unroll
    for (int i = 0; i < 16; ++i) {
        unsigned off = ((i & 1)        ? (1u << P0) : 0u)
                     | (((i >> 1) & 1) ? (1u << P1) : 0u)
                     | (((i >> 2) & 1) ? (1u << P2) : 0u)
                     | (((i >> 3) & 1) ? (1u << P3) : 0u);
        float lo, hi; upk2(p[i], lo, hi);
        sm[SWZ(x | off)] = make_float2(lo, hi);
    }
}

template <int PASS>
__global__ __launch_bounds__(256, 3)
void qsim_pass(const float* __restrict__ in, float* __restrict__ out,
               const float* __restrict__ gates)
{
    __shared__ float2 sm[4096];
    __shared__ u64 sWa[4][16];   // [gate-in-pass][g*4+h] = (wr,wr)
    __shared__ u64 sWb[4][16];   // (wi,wi)

    const unsigned tid = threadIdx.x;
    const unsigned b = blockIdx.x;
    const unsigned hi = (PASS == 0) ? (b << 12)
                                    : (((b & 7u) << 8) | ((b >> 3) << 15));

    // Build packed weights in smem (128 threads, one entry each).
    if (tid < 128) {
        const unsigned gate = tid >> 5;          // 0..3 within pass
        const unsigned k = (tid >> 1) & 15;      // 0..15
        const float* gp = gates + (PASS * 4 + gate) * 32;
        if (tid & 1) sWb[gate][k] = pk2(gp[16 + k], gp[16 + k]);
        else         sWa[gate][k] = pk2(gp[k], gp[k]);
    }

    // ---- Stage tile: LDG.128 per plane, conflict-free STS.64 ----
    #pragma unroll
    for (int j = 0; j < 4; ++j) {
        unsigned a = (tid + 256u * j) * 4u;
        unsigned g = (PASS == 0) ? (hi | a)
                                 : (hi | ((a >> 8) << 11) | (a & 255u));
        float4 r4 = *(const float4*)(in + g);
        float4 m4 = *(const float4*)(in + NSTATE + g);
        sm[SWZ(a + 0)] = make_float2(r4.x, m4.x);
        sm[SWZ(a + 1)] = make_float2(r4.y, m4.y);
        sm[SWZ(a + 2)] = make_float2(r4.z, m4.z);
        sm[SWZ(a + 3)] = make_float2(r4.w, m4.w);
    }
    __syncthreads();

    // ---- Two fused gate pairs ----
    if (PASS == 0) apply_pair<0, 1, 7, 8>(sm, tid, sWa[0], sWb[0], sWa[1], sWb[1]);
    else           apply_pair<4, 5, 8, 9>(sm, tid, sWa[0], sWb[0], sWa[1], sWb[1]);
    __syncthreads();
    if (PASS == 0) apply_pair<2, 3, 9, 10>(sm, tid, sWa[2], sWb[2], sWa[3], sWb[3]);
    else           apply_pair<6, 7, 10, 11>(sm, tid, sWa[2], sWb[2], sWa[3], sWb[3]);
    __syncthreads();

    // ---- Write back: STG.128 per plane ----
    #pragma unroll
    for (int j = 0; j < 4; ++j) {
        unsigned a = (tid + 256u * j) * 4u;
        unsigned g = (PASS == 0) ? (hi | a)
                                 : (hi | ((a >> 8) << 11) | (a & 255u));
        float2 v0 = sm[SWZ(a + 0)], v1 = sm[SWZ(a + 1)];
        float2 v2 = sm[SWZ(a + 2)], v3 = sm[SWZ(a + 3)];
        *(float4*)(out + g)          = make_float4(v0.x, v1.x, v2.x, v3.x);
        *(float4*)(out + NSTATE + g) = make_float4(v0.y, v1.y, v2.y, v3.y);
    }
}

extern "C" void kernel_launch(void* const* d_in, const int* in_sizes, int n_in,
                              void* d_out, int out_size)
{
    const float* state = (const float*)d_in[0];   // 2 * 2^24 floats (re, im planes)
    const float* gates = (const float*)d_in[1];   // 8 * 2 * 4 * 4 floats
    float* out = (float*)d_out;

    qsim_pass<0><<<4096, 256>>>(state, out, gates);   // steps 0..3
    qsim_pass<1><<<4096, 256>>>(out, out, gates);     // steps 4..7 (in place, disjoint)
}

// round 5
// speedup vs baseline: 1.2970x; 1.2970x over previous
#include <cuda_runtime.h>

// 24-qubit state-vector sim, 8 two-qubit gates, step s -> qubits (s, s+7).
// Pass A: steps 0..5 (amp bits {0..5,7..12} -> 12-bit tile, 32KB smem),
//         fused as 3 register pairs of 16-amp supergroups.
// Pass B: steps 6,7 (amp bits {6,7,13,14}) streamed gmem->regs->gmem, no smem.
// Weights packed (w,w) live in smem, streamed row-wise (broadcast LDS.64).
// All amp-array indices are LITERAL constants (R4's __constant__ tables forced
// p[]/o[] to local memory -> the 297us regression).
// Swizzle folds tile bits 5,6,8 into the bank bits: GF(2) rank-5 for staging
// and all three pair access patterns -> zero bank conflicts.

#define NSTATE (1u << 24)
typedef unsigned long long u64;

__device__ __forceinline__ u64 pk2(float lo, float hi) {
    u64 r; asm("mov.b64 %0, {%1, %2};" : "=l"(r) : "f"(lo), "f"(hi)); return r;
}
__device__ __forceinline__ void upk2(u64 v, float& lo, float& hi) {
    asm("mov.b64 {%0, %1}, %2;" : "=f"(lo), "=f"(hi) : "l"(v));
}
__device__ __forceinline__ u64 ffma2(u64 a, u64 b, u64 c) {
    u64 d; asm("fma.rn.f32x2 %0, %1, %2, %3;" : "=l"(d) : "l"(a), "l"(b), "l"(c)); return d;
}
__device__ __forceinline__ u64 fmul2(u64 a, u64 b) {
    u64 d; asm("mul.rn.f32x2 %0, %1, %2;" : "=l"(d) : "l"(a), "l"(b)); return d;
}
__device__ __forceinline__ unsigned SWZ(unsigned x) {
    return x ^ (((x >> 5) & 1u) * 10u) ^ (((x >> 6) & 1u) * 21u)
             ^ (((x >> 8) & 1u) * 3u);
}

// One output row: dst = sum_h W[row][h] * src_h (complex, two f32x2 accs).
#define CROW(s0, s1, s2, s3, dst)                                         \
    {                                                                      \
        u64 a1 = fmul2(p[s0], w0);                                        \
        a1 = ffma2(p[s1], w1, a1);                                        \
        a1 = ffma2(p[s2], w2, a1);                                        \
        a1 = ffma2(p[s3], w3, a1);                                        \
        u64 a2 = fmul2(p[s0], v0);                                        \
        a2 = ffma2(p[s1], v1, a2);                                        \
        a2 = ffma2(p[s2], v2, a2);                                        \
        a2 = ffma2(p[s3], v3, a2);                                        \
        float r1, i1, r2, i2; upk2(a1, r1, i1); upk2(a2, r2, i2);          \
        dst = pk2(r1 - i2, i1 + r2);                                      \
    }

// Apply a 4x4 gate to two independent quads (one "half": 8 amps, all literal).
// Weights streamed per row from smem (swa=(wr,wr)x16, swb=(wi,wi)x16).
#define GATE_HALF(swa, swb, a0, a1_, a2_, a3, b0, b1_, b2_, b3)            \
    {                                                                      \
        u64 oh[8];                                                         \
        _Pragma("unroll")                                                  \
        for (int g = 0; g < 4; ++g) {                                      \
            u64 w0 = (swa)[g*4+0], w1 = (swa)[g*4+1];                      \
            u64 w2 = (swa)[g*4+2], w3 = (swa)[g*4+3];                      \
            u64 v0 = (swb)[g*4+0], v1 = (swb)[g*4+1];                      \
            u64 v2 = (swb)[g*4+2], v3 = (swb)[g*4+3];                      \
            CROW(a0, a1_, a2_, a3, oh[g]);                                 \
            CROW(b0, b1_, b2_, b3, oh[4+g]);                               \
        }                                                                  \
        p[a0] = oh[0]; p[a1_] = oh[1]; p[a2_] = oh[2]; p[a3] = oh[3];      \
        p[b0] = oh[4]; p[b1_] = oh[5]; p[b2_] = oh[6]; p[b3] = oh[7];      \
    }

// Gate A varies group bits (0,2); gate B varies (1,3). Two halves each.
#define GATE_A(sw) \
    GATE_HALF((sw), (sw)+16, 0, 1, 4, 5,   2, 3, 6, 7)                     \
    GATE_HALF((sw), (sw)+16, 8, 9, 12, 13, 10, 11, 14, 15)
#define GATE_B(sw) \
    GATE_HALF((sw), (sw)+16, 0, 2, 8, 10,  1, 3, 9, 11)                    \
    GATE_HALF((sw), (sw)+16, 4, 6, 12, 14, 5, 7, 13, 15)

// ---------------- Pass A: steps 0..5 in shared memory ----------------
template <int P0, int P1, int P2, int P3>
__device__ __forceinline__ void apply_pair(float2* sm, unsigned tid,
                                           const u64* __restrict__ sw0,
                                           const u64* __restrict__ sw1)
{
    unsigned x = tid;   // 256 threads, 256 supergroups: one each
    x = ((x & ~((1u << P0) - 1u)) << 1) | (x & ((1u << P0) - 1u));
    x = ((x & ~((1u << P1) - 1u)) << 1) | (x & ((1u << P1) - 1u));
    x = ((x & ~((1u << P2) - 1u)) << 1) | (x & ((1u << P2) - 1u));
    x = ((x & ~((1u << P3) - 1u)) << 1) | (x & ((1u << P3) - 1u));

    u64 p[16];
    #pragma unroll
    for (int i = 0; i < 16; ++i) {
        unsigned off = ((i & 1)        ? (1u << P0) : 0u)
                     | (((i >> 1) & 1) ? (1u << P1) : 0u)
                     | (((i >> 2) & 1) ? (1u << P2) : 0u)
                     | (((i >> 3) & 1) ? (1u << P3) : 0u);
        float2 v = sm[SWZ(x | off)];
        p[i] = pk2(v.x, v.y);
    }

    GATE_A(sw0);   // first gate of pair: bits (P0,P2)
    GATE_B(sw1);   // second gate: bits (P1,P3)

    #pragma unroll
    for (int i = 0; i < 16; ++i) {
        unsigned off = ((i & 1)        ? (1u << P0) : 0u)
                     | (((i >> 1) & 1) ? (1u << P1) : 0u)
                     | (((i >> 2) & 1) ? (1u << P2) : 0u)
                     | (((i >> 3) & 1) ? (1u << P3) : 0u);
        float lo, hi; upk2(p[i], lo, hi);
        sm[SWZ(x | off)] = make_float2(lo, hi);
    }
}

__global__ __launch_bounds__(256, 3)
void qsim_passA(const float* __restrict__ in, float* __restrict__ out,
                const float* __restrict__ gates)
{
    __shared__ float2 sm[4096];
    __shared__ u64 sW[192];   // gates 0..5: [k*32 + 0..15]=(wr,wr), [+16..31]=(wi,wi)

    const unsigned tid = threadIdx.x;
    const unsigned b = blockIdx.x;   // bit0 -> amp bit 6; bits 1..11 -> amp bits 13..23
    const unsigned hi = ((b & 1u) << 6) | ((b >> 1) << 13);

    if (tid < 192) { float w = gates[tid]; sW[tid] = pk2(w, w); }

    // Stage tile: amp = hi | ((a>>6)<<7) | (a&63). LDG.128, conflict-free STS.
    #pragma unroll
    for (int j = 0; j < 4; ++j) {
        unsigned a = (tid + 256u * j) * 4u;
        unsigned g = hi | ((a >> 6) << 7) | (a & 63u);
        float4 r4 = *(const float4*)(in + g);
        float4 m4 = *(const float4*)(in + NSTATE + g);
        sm[SWZ(a + 0)] = make_float2(r4.x, m4.x);
        sm[SWZ(a + 1)] = make_float2(r4.y, m4.y);
        sm[SWZ(a + 2)] = make_float2(r4.z, m4.z);
        sm[SWZ(a + 3)] = make_float2(r4.w, m4.w);
    }
    __syncthreads();

    // steps (0,1): amp bits (0,7),(1,8) -> tile bits {0,1,6,7}
    apply_pair<0, 1, 6, 7>(sm, tid, sW + 0 * 32, sW + 1 * 32);
    __syncthreads();
    // steps (2,3): amp bits (2,9),(3,10) -> tile bits {2,3,8,9}
    apply_pair<2, 3, 8, 9>(sm, tid, sW + 2 * 32, sW + 3 * 32);
    __syncthreads();
    // steps (4,5): amp bits (4,11),(5,12) -> tile bits {4,5,10,11}
    apply_pair<4, 5, 10, 11>(sm, tid, sW + 4 * 32, sW + 5 * 32);
    __syncthreads();

    #pragma unroll
    for (int j = 0; j < 4; ++j) {
        unsigned a = (tid + 256u * j) * 4u;
        unsigned g = hi | ((a >> 6) << 7) | (a & 63u);
        float2 v0 = sm[SWZ(a + 0)], v1 = sm[SWZ(a + 1)];
        float2 v2 = sm[SWZ(a + 2)], v3 = sm[SWZ(a + 3)];
        *(float4*)(out + g)          = make_float4(v0.x, v1.x, v2.x, v3.x);
        *(float4*)(out + NSTATE + g) = make_float4(v0.y, v1.y, v2.y, v3.y);
    }
}

// ---------------- Pass B: steps 6,7 streamed through registers ----------------
__global__ __launch_bounds__(256, 4)
void qsim_passB(float* __restrict__ st, const float* __restrict__ gates)
{
    __shared__ u64 sW[64];   // gate 6 then gate 7, packed (w,w)
    const unsigned tid = threadIdx.x;
    if (tid < 64) { float w = gates[192 + tid]; sW[tid] = pk2(w, w); }
    __syncthreads();

    // thread t owns the 16-amp supergroup over amp bits {6,7,13,14}
    unsigned x = blockIdx.x * 256u + tid;
    x = ((x & ~63u)    << 1) | (x & 63u);      // insert 0 at bit 6
    x = ((x & ~127u)   << 1) | (x & 127u);     // bit 7
    x = ((x & ~8191u)  << 1) | (x & 8191u);    // bit 13
    x = ((x & ~16383u) << 1) | (x & 16383u);   // bit 14

    u64 p[16];
    #pragma unroll
    for (int i = 0; i < 16; ++i) {
        unsigned off = ((i & 1)        ? 64u    : 0u)
                     | (((i >> 1) & 1) ? 128u   : 0u)
                     | (((i >> 2) & 1) ? 8192u  : 0u)
                     | (((i >> 3) & 1) ? 16384u : 0u);
        unsigned g = x | off;
        p[i] = pk2(st[g], st[NSTATE + g]);   // coalesced: lanes vary amp bits 0..4
    }

    {   const u64* sw0 = sW;        // gate 6: amp bits (6,13) = group bits (0,2)
        GATE_A(sw0) }
    {   const u64* sw1 = sW + 32;   // gate 7: amp bits (7,14) = group bits (1,3)
        GATE_B(sw1) }

    #pragma unroll
    for (int i = 0; i < 16; ++i) {
        unsigned off = ((i & 1)        ? 64u    : 0u)
                     | (((i >> 1) & 1) ? 128u   : 0u)
                     | (((i >> 2) & 1) ? 8192u  : 0u)
                     | (((i >> 3) & 1) ? 16384u : 0u);
        unsigned g = x | off;
        float lo, hi; upk2(p[i], lo, hi);
        st[g] = lo;
        st[NSTATE + g] = hi;
    }
}

extern "C" void kernel_launch(void* const* d_in, const int* in_sizes, int n_in,
                              void* d_out, int out_size)
{
    const float* state = (const float*)d_in[0];   // 2 * 2^24 floats (re, im planes)
    const float* gates = (const float*)d_in[1];   // 8 * 2 * 4 * 4 floats
    float* out = (float*)d_out;

    qsim_passA<<<4096, 256>>>(state, out, gates);   // steps 0..5
    qsim_passB<<<4096, 256>>>(out, gates);          // steps 6..7 (in place, disjoint)
}